// round 8
// baseline (speedup 1.0000x reference)
#include <cuda_runtime.h>
#include <cuda_fp16.h>

typedef unsigned long long u64;
typedef unsigned int u32;

#define K_CODES 8192
#define EDIM 128
#define TM 128
#define TN 128
#define N_TILES (K_CODES / TN)    // 64
#define SRB 144                   // smem row stride in bytes (int8 rows, conflict-free)
#define SRW 36                    // row stride in words
#define A_BYTES (128 * SRB)       // 18432
#define STAGE_BYTES (128 * SRB)
#define ZS_OFF (3 * A_BYTES)                 // float[128] zsq
#define SB_OFF (ZS_OFF + 512)                // u64[128] best
#define SC_OFF (SB_OFF + 1024)               // float[128] 2*scale
#define SMEM_TOTAL (SC_OFF + 512)
#define DELTA 8e-3f
#define NCAND 48
#define AE 16256.0f               // emb quant scale = 127*128

__device__ float  d_esq[K_CODES];
__device__ float  d_zsq[32768];
__device__ __align__(16) u32 d_emb_q[K_CODES * 32];   // int8 image of emb
__device__ int    d_counts[K_CODES];
__device__ int    d_idx[32768];
__device__ u64    d_minkey[32768];
__device__ u64    d_cand[32768 * NCAND];
__device__ double d_sumsq;

// ---------------- helpers ----------------
__device__ __forceinline__ u32 smem_u32(const void* p) {
    u32 a; asm("{ .reg .u64 t; cvta.to.shared.u64 t, %1; cvt.u32.u64 %0, t; }" : "=r"(a) : "l"(p));
    return a;
}
__device__ __forceinline__ u32 fkey(float s) {
    u32 b = __float_as_uint(s);
    return (b & 0x80000000u) ? ~b : (b | 0x80000000u);
}
__device__ __forceinline__ float unfkey(u32 k) {
    u32 b = (k & 0x80000000u) ? (k & 0x7FFFFFFFu) : ~k;
    return __uint_as_float(b);
}
__device__ __forceinline__ void cp16(u32 dst, const void* src) {
    asm volatile("cp.async.cg.shared.global [%0], [%1], 16;" :: "r"(dst), "l"(src) : "memory");
}
// int8 IMMA: m16n8k32, s32 accumulate
__device__ __forceinline__ void mma8i(int* c, const u32* a, const u32* b) {
    asm volatile(
        "mma.sync.aligned.m16n8k32.row.col.s32.s8.s8.s32 "
        "{%0,%1,%2,%3}, {%4,%5,%6,%7}, {%8,%9}, {%0,%1,%2,%3};"
        : "+r"(c[0]), "+r"(c[1]), "+r"(c[2]), "+r"(c[3])
        : "r"(a[0]), "r"(a[1]), "r"(a[2]), "r"(a[3]), "r"(b[0]), "r"(b[1]));
}
__device__ __forceinline__ void ldsm4(u32* r, u32 addr) {
    asm volatile("ldmatrix.sync.aligned.m8n8.x4.shared.b16 {%0,%1,%2,%3}, [%4];"
        : "=r"(r[0]), "=r"(r[1]), "=r"(r[2]), "=r"(r[3]) : "r"(addr));
}
__device__ __forceinline__ u32 packq(float a, float b, float c, float d, float sc) {
    int q0 = __float2int_rn(a * sc), q1 = __float2int_rn(b * sc);
    int q2 = __float2int_rn(c * sc), q3 = __float2int_rn(d * sc);
    return ((u32)q0 & 0xffu) | (((u32)q1 & 0xffu) << 8)
         | (((u32)q2 & 0xffu) << 16) | (((u32)q3 & 0xffu) << 24);
}
__device__ __forceinline__ void top3(u64& b1, u64& b2, u64& b3, u64 k) {
    if (k < b1) { b3 = b2; b2 = b1; b1 = k; }
    else if (k < b2) { b3 = b2; b2 = k; }
    else if (k < b3) { b3 = k; }
}

// ---------- kernel 0: |e_k|^2, int8 emb image, zero counts/sumsq ----------
__global__ void k_init(const float* __restrict__ emb) {
    int k = blockIdx.x * blockDim.x + threadIdx.x;
    if (k < K_CODES) {
        const float4* row = (const float4*)(emb + (size_t)k * EDIM);
        float s = 0.f;
#pragma unroll
        for (int i = 0; i < EDIM / 4; i++) {
            float4 v = row[i];
            s += v.x * v.x + v.y * v.y + v.z * v.z + v.w * v.w;
            d_emb_q[k * 32 + i] = packq(v.x, v.y, v.z, v.w, AE);
        }
        d_esq[k] = s;
        d_counts[k] = 0;
    }
    if (blockIdx.x == 0 && threadIdx.x == 0) d_sumsq = 0.0;
}

// ---------- main: int8 IMMA screening GEMM + top-3 candidates ----------
extern "C" __global__ void __launch_bounds__(256, 1)
k_main(const float* __restrict__ z, const float* __restrict__ emb) {
    extern __shared__ char smem[];
    u32*   A32   = (u32*)smem;                        // [128][36] int8 rows
    float* zsmem = (float*)(smem + ZS_OFF);           // [128] zsq
    u64*   sbest = (u64*)(smem + SB_OFF);             // [128]
    float* ssc   = (float*)(smem + SC_OFF);           // [128] 2*dequant scale

    const int tid  = threadIdx.x;
    const int wid  = tid >> 5;
    const int lane = tid & 31;
    const int lr   = lane >> 2;
    const int lc   = lane & 3;
    const int wm   = (wid & 1) * 64;
    const int wn   = (wid >> 1) * 32;
    const int rowBase = blockIdx.x * TM;

    const u32 smb   = smem_u32(smem);
    const u32 bsOff = smb + A_BYTES;

    // ldmatrix base addresses (byte offsets); kb adds 32B per k-step
    u32 aBase[4], bBase[2];
#pragma unroll
    for (int i = 0; i < 4; i++)
        aBase[i] = smb + (u32)((wm + i * 16 + ((lane >> 3) & 1) * 8 + (lane & 7)) * SRB
                   + (lane >> 4) * 16);
#pragma unroll
    for (int jj = 0; jj < 2; jj++)
        bBase[jj] = (u32)((wn + jj * 16 + ((lane >> 4) & 1) * 8 + (lane & 7)) * SRB
                   + ((lane >> 3) & 1) * 16);

    // prefetch tile 0 (int8 image: 128B/row = 8 chunks)
    {
#pragma unroll
        for (int i = 0; i < 4; i++) {
            int idx = tid + i * 256;                  // 0..1023
            int r = idx >> 3, seg = idx & 7;
            cp16(bsOff + (u32)(r * SRB + seg * 16), d_emb_q + r * 32 + seg * 4);
        }
        asm volatile("cp.async.commit_group;" ::: "memory");
    }

    // prologue: zsq (exact, round-2-identical order) + per-row int8 quantize
    if (tid < 128) {
        const float4* zr = (const float4*)(z + (size_t)(rowBase + tid) * EDIM);
        float s = 0.f, ma = 0.f;
#pragma unroll
        for (int q = 0; q < 32; q++) {
            float4 v = zr[q];
            s += v.x * v.x + v.y * v.y + v.z * v.z + v.w * v.w;
            ma = fmaxf(ma, fmaxf(fmaxf(fabsf(v.x), fabsf(v.y)),
                                 fmaxf(fabsf(v.z), fabsf(v.w))));
        }
        float az = 127.f / fmaxf(ma, 1e-30f);
#pragma unroll
        for (int q = 0; q < 32; q++) {
            float4 v = zr[q];
            A32[tid * SRW + q] = packq(v.x, v.y, v.z, v.w, az);
        }
        d_zsq[rowBase + tid] = s;
        zsmem[tid] = s;
        ssc[tid]   = 2.f * ma / (127.f * AE);         // folds the 2x
        sbest[tid] = ~0ULL;
    }
    __syncthreads();

    float zrow[4][2], zsc[4][2];
#pragma unroll
    for (int i = 0; i < 4; i++) {
        zrow[i][0] = zsmem[wm + i * 16 + lr];      zsc[i][0] = ssc[wm + i * 16 + lr];
        zrow[i][1] = zsmem[wm + i * 16 + lr + 8];  zsc[i][1] = ssc[wm + i * 16 + lr + 8];
    }

    u64 best1[4][2], best2[4][2], best3[4][2];
#pragma unroll
    for (int i = 0; i < 4; i++)
#pragma unroll
        for (int s = 0; s < 2; s++) { best1[i][s] = ~0ULL; best2[i][s] = ~0ULL; best3[i][s] = ~0ULL; }

#pragma unroll 1
    for (int tile = 0; tile < N_TILES; tile++) {
        const int st = tile & 1;
        const int colBase = tile * TN;

        float eq[4][2];
#pragma unroll
        for (int j = 0; j < 4; j++) {
            int c0 = colBase + wn + j * 8 + 2 * lc;
            eq[j][0] = d_esq[c0];
            eq[j][1] = d_esq[c0 + 1];
        }

        if (tile + 1 < N_TILES) {
            const u32* src = d_emb_q + (size_t)(colBase + TN) * 32;
            u32 dstb = bsOff + (st ^ 1) * STAGE_BYTES;
#pragma unroll
            for (int i = 0; i < 4; i++) {
                int idx = tid + i * 256;
                int r = idx >> 3, seg = idx & 7;
                cp16(dstb + (u32)(r * SRB + seg * 16), src + r * 32 + seg * 4);
            }
            asm volatile("cp.async.commit_group;" ::: "memory");
            asm volatile("cp.async.wait_group 1;" ::: "memory");
        } else {
            asm volatile("cp.async.wait_group 0;" ::: "memory");
        }
        __syncthreads();

        const u32 bSt = bsOff + st * STAGE_BYTES;

        int acc[4][4][4];
#pragma unroll
        for (int i = 0; i < 4; i++)
#pragma unroll
            for (int j = 0; j < 4; j++)
#pragma unroll
                for (int c = 0; c < 4; c++) acc[i][j][c] = 0;

#pragma unroll
        for (int kb = 0; kb < 4; kb++) {              // K=128 / 32
            const u32 kOff = (u32)kb * 32;
            u32 af[4][4], bf[2][4];
#pragma unroll
            for (int i = 0; i < 4; i++) ldsm4(af[i], aBase[i] + kOff);
#pragma unroll
            for (int jj = 0; jj < 2; jj++) ldsm4(bf[jj], bSt + bBase[jj] + kOff);
#pragma unroll
            for (int i = 0; i < 4; i++) {
                mma8i(acc[i][0], af[i], &bf[0][0]);
                mma8i(acc[i][1], af[i], &bf[0][2]);
                mma8i(acc[i][2], af[i], &bf[1][0]);
                mma8i(acc[i][3], af[i], &bf[1][2]);
            }
        }

        // approx epilogue: dequant + grid formula, top-3 per thread
#pragma unroll
        for (int i = 0; i < 4; i++) {
#pragma unroll
            for (int j = 0; j < 4; j++) {
                int cg0 = colBase + wn + j * 8 + 2 * lc;
#pragma unroll
                for (int s = 0; s < 2; s++) {
                    float c0 = __int2float_rn(acc[i][j][2 * s + 0]);
                    float c1 = __int2float_rn(acc[i][j][2 * s + 1]);
                    float d0 = (zrow[i][s] + eq[j][0]) - c0 * zsc[i][s];
                    float d1 = (zrow[i][s] + eq[j][1]) - c1 * zsc[i][s];
                    top3(best1[i][s], best2[i][s], best3[i][s],
                         ((u64)fkey(d0) << 13) | (u32)cg0);
                    top3(best1[i][s], best2[i][s], best3[i][s],
                         ((u64)fkey(d1) << 13) | (u32)(cg0 + 1));
                }
            }
        }
        __syncthreads();
    }

    const int slot = (wid >> 1) * 4 + lc;             // 0..15 per row
#pragma unroll
    for (int i = 0; i < 4; i++)
#pragma unroll
        for (int s = 0; s < 2; s++) {
            int rl = wm + i * 16 + lr + s * 8;
            atomicMin(&sbest[rl], best1[i][s]);
            u64* c = &d_cand[(size_t)(rowBase + rl) * NCAND + slot * 3];
            c[0] = best1[i][s];
            c[1] = best2[i][s];
            c[2] = best3[i][s];
        }
    __syncthreads();
    if (tid < 128) d_minkey[rowBase + tid] = sbest[tid];
}

// ---------- rescore: exact fp32 dot on candidates, grid-exact argmin ----------
__global__ void k_rescore(const float* __restrict__ z, const float* __restrict__ emb) {
    int warp = (blockIdx.x * blockDim.x + threadIdx.x) >> 5;
    int lane = threadIdx.x & 31;
    int r = warp;

    u64 mk = d_minkey[r];
    float dmin = unfkey((u32)(mk >> 13));
    u32 thr = fkey(dmin + DELTA);

    u64 mykey = ~0ULL;
#pragma unroll
    for (int it = 0; it < 2; it++) {
        int ci = lane + it * 32;
        if (ci < NCAND) {
            u64 key = d_cand[(size_t)r * NCAND + ci];
            if ((u32)(key >> 13) <= thr) {
                int idx = (int)(key & 0x1FFFULL);
                const float4* zr = (const float4*)(z + (size_t)r * EDIM);
                const float4* er = (const float4*)(emb + (size_t)idx * EDIM);
                float dot = 0.f;
#pragma unroll
                for (int q = 0; q < 32; q++) {
                    float4 a = zr[q], b = er[q];
                    dot += a.x * b.x + a.y * b.y + a.z * b.z + a.w * b.w;
                }
                float t = d_zsq[r] + d_esq[idx];      // fl(zsq+esq)
                float d = t - 2.f * dot;              // fl(t - 2*dot): grid-exact
                u64 k2 = ((u64)fkey(d) << 13) | (u32)idx;
                if (k2 < mykey) mykey = k2;
            }
        }
    }
#pragma unroll
    for (int off = 16; off; off >>= 1) {
        u64 o = __shfl_xor_sync(0xffffffffu, mykey, off);
        if (o < mykey) mykey = o;
    }
    if (lane == 0) d_idx[r] = (int)(mykey & 0x1FFFULL);
}

// ---------- gather + straight-through out + sums + counts ----------
__global__ void k_gather(const float* __restrict__ z, const float* __restrict__ emb,
                         float* __restrict__ out) {
    __shared__ float red[8];
    int e4 = blockIdx.x * blockDim.x + threadIdx.x;
    int row = e4 >> 5;
    int d4  = e4 & 31;
    int k = d_idx[row];
    float4 q  = ((const float4*)(emb + (size_t)k * EDIM))[d4];
    float4 zz = ((const float4*)z)[e4];
    float4 o;
    float s = 0.f, df;
    df = q.x - zz.x; o.x = zz.x + df; s += df * df;
    df = q.y - zz.y; o.y = zz.y + df; s += df * df;
    df = q.z - zz.z; o.z = zz.z + df; s += df * df;
    df = q.w - zz.w; o.w = zz.w + df; s += df * df;
    ((float4*)out)[e4] = o;
    if (d4 == 0) atomicAdd(&d_counts[k], 1);
#pragma unroll
    for (int off = 16; off; off >>= 1) s += __shfl_xor_sync(0xffffffffu, s, off);
    int lane = threadIdx.x & 31, w = threadIdx.x >> 5;
    if (lane == 0) red[w] = s;
    __syncthreads();
    if (threadIdx.x == 0) {
        float bs = 0.f;
#pragma unroll
        for (int i = 0; i < 8; i++) bs += red[i];
        atomicAdd(&d_sumsq, (double)bs);
    }
}

// ---------- perplexity + commit loss ----------
__global__ void k_final(float* __restrict__ out, int n_rows) {
    __shared__ float red[256];
    float acc = 0.f;
    float invN = 1.f / (float)n_rows;
    for (int k = threadIdx.x; k < K_CODES; k += 256) {
        float e = (float)d_counts[k] * invN;
        acc += e * logf(e + 1e-8f);
    }
    red[threadIdx.x] = acc;
    __syncthreads();
    for (int s = 128; s; s >>= 1) {
        if (threadIdx.x < s) red[threadIdx.x] += red[threadIdx.x + s];
        __syncthreads();
    }
    if (threadIdx.x == 0) {
        float m = (float)(d_sumsq / (double)((size_t)n_rows * EDIM));
        out[(size_t)n_rows * EDIM]     = 0.25f * m + m;
        out[(size_t)n_rows * EDIM + 1] = expf(-red[0]);
    }
}

extern "C" void kernel_launch(void* const* d_in, const int* in_sizes, int n_in,
                              void* d_out, int out_size) {
    const float* z   = (const float*)d_in[0];
    const float* emb = (const float*)d_in[1];
    float* out = (float*)d_out;
    int n_rows = in_sizes[0] / EDIM;                  // 32768

    cudaFuncSetAttribute(k_main, cudaFuncAttributeMaxDynamicSharedMemorySize, SMEM_TOTAL);

    k_init<<<K_CODES / 256, 256>>>(emb);
    k_main<<<n_rows / TM, 256, SMEM_TOTAL>>>(z, emb);
    k_rescore<<<n_rows / 8, 256>>>(z, emb);
    k_gather<<<(n_rows * (EDIM / 4)) / 256, 256>>>(z, emb, out);
    k_final<<<1, 256>>>(out, n_rows);
}

// round 9
// speedup vs baseline: 1.7807x; 1.7807x over previous
#include <cuda_runtime.h>
#include <cuda_fp16.h>

typedef unsigned long long u64;
typedef unsigned int u32;

#define K_CODES 8192
#define EDIM 128
#define TM 32                     // rows per row-tile
#define N_ROWTILES 1024
#define TN 128
#define N_TILES (K_CODES / TN)    // 64
#define SAW 68                    // A16 row stride in words (136 halfs)
#define SAH 136                   // B row stride in halfs
#define STAGE_BYTES (128 * SAH * 2)   // 34816
#define A16_OFF 0                 // 32*68*4 = 8704
#define ASF_OFF 8704              // 32*132*4 = 16896
#define B_OFF 25600               // 2 stages x 34816 -> ends 95232
#define ZS_OFF 95232              // float[32]
#define SB_OFF 95360              // u64[32]
#define SMEM_TOTAL 96000
#define DELTA 3e-3f

__device__ float  d_esq[K_CODES];
__device__ float  d_zsq[32768];
__device__ __align__(16) u32 d_emb_h[K_CODES * 64];   // fp16 image of emb
__device__ int    d_counts[K_CODES];
__device__ u64    d_minkey[32768];
__device__ u64    d_cand[32768 * 64];
__device__ double d_sumsq;
__device__ u32    d_tilectr;

// ---------------- helpers ----------------
__device__ __forceinline__ u32 smem_u32(const void* p) {
    u32 a; asm("{ .reg .u64 t; cvta.to.shared.u64 t, %1; cvt.u32.u64 %0, t; }" : "=r"(a) : "l"(p));
    return a;
}
__device__ __forceinline__ u32 fkey(float s) {
    u32 b = __float_as_uint(s);
    return (b & 0x80000000u) ? ~b : (b | 0x80000000u);
}
__device__ __forceinline__ float unfkey(u32 k) {
    u32 b = (k & 0x80000000u) ? (k & 0x7FFFFFFFu) : ~k;
    return __uint_as_float(b);
}
__device__ __forceinline__ void cp16(u32 dst, const void* src) {
    asm volatile("cp.async.cg.shared.global [%0], [%1], 16;" :: "r"(dst), "l"(src) : "memory");
}
__device__ __forceinline__ void mma16h(u32* c, const u32* a, const u32* b) {
    asm volatile(
        "mma.sync.aligned.m16n8k16.row.col.f16.f16.f16.f16 "
        "{%0,%1}, {%2,%3,%4,%5}, {%6,%7}, {%0,%1};"
        : "+r"(c[0]), "+r"(c[1])
        : "r"(a[0]), "r"(a[1]), "r"(a[2]), "r"(a[3]), "r"(b[0]), "r"(b[1]));
}
__device__ __forceinline__ void ldsm4(u32* r, u32 addr) {
    asm volatile("ldmatrix.sync.aligned.m8n8.x4.shared.b16 {%0,%1,%2,%3}, [%4];"
        : "=r"(r[0]), "=r"(r[1]), "=r"(r[2]), "=r"(r[3]) : "r"(addr));
}
__device__ __forceinline__ u32 h2u(float x, float y) {
    __half2 h = __floats2half2_rn(x, y);
    return *(u32*)&h;
}
__device__ __forceinline__ void top2(u64& b1, u64& b2, u64 k) {
    if (k < b1) { b2 = b1; b1 = k; }
    else if (k < b2) { b2 = k; }
}

// ---------- kernel 0: |e_k|^2, fp16 emb image, zero counts/sumsq/ctr ----------
__global__ void k_init(const float* __restrict__ emb) {
    int k = blockIdx.x * blockDim.x + threadIdx.x;
    if (k < K_CODES) {
        const float4* row = (const float4*)(emb + (size_t)k * EDIM);
        float s = 0.f;
#pragma unroll
        for (int i = 0; i < EDIM / 4; i++) {
            float4 v = row[i];
            s += v.x * v.x + v.y * v.y + v.z * v.z + v.w * v.w;
            d_emb_h[k * 64 + i * 2]     = h2u(v.x, v.y);
            d_emb_h[k * 64 + i * 2 + 1] = h2u(v.z, v.w);
        }
        d_esq[k] = s;
        d_counts[k] = 0;
    }
    if (blockIdx.x == 0 && threadIdx.x == 0) { d_sumsq = 0.0; d_tilectr = 0; }
}

// ---------- main: persistent fp16 screening GEMM + top-2 candidates ----------
extern "C" __global__ void __launch_bounds__(256, 2)
k_main(const float* __restrict__ z, const float* __restrict__ emb) {
    extern __shared__ char smem[];
    u32*    A32   = (u32*)(smem + A16_OFF);           // [32][68] half2 words
    float4* Asf4  = (float4*)(smem + ASF_OFF);        // [32][33] float4 staging
    float*  zsmem = (float*)(smem + ZS_OFF);          // [32]
    u64*    sbest = (u64*)(smem + SB_OFF);            // [32]
    __shared__ u32 s_tile;

    const int tid  = threadIdx.x;
    const int wid  = tid >> 5;
    const int lane = tid & 31;
    const int lr   = lane >> 2;
    const int lc   = lane & 3;
    const int wn   = wid * 16;                        // warp n offset (8 warps x n16)

    const u32 smb   = smem_u32(smem);
    const u32 bsOff = smb + B_OFF;

    // ldmatrix base addresses
    u32 aBase[2];
#pragma unroll
    for (int i = 0; i < 2; i++)
        aBase[i] = smb + (u32)((i * 16 + ((lane >> 3) & 1) * 8 + (lane & 7)) * (SAW * 4)
                   + (lane >> 4) * 16);
    const u32 bBase = (u32)((wn + ((lane >> 4) & 1) * 8 + (lane & 7)) * (SAH * 2)
                   + ((lane >> 3) & 1) * 16);

    for (;;) {
        if (tid == 0) s_tile = atomicAdd(&d_tilectr, 1u);
        __syncthreads();
        const u32 t = s_tile;
        if (t >= N_ROWTILES) break;
        const int rowBase = (int)t * TM;

        // prefetch B tile 0 into stage 0
        {
#pragma unroll
            for (int i = 0; i < 8; i++) {
                int idx = tid + i * 256;
                int r = idx >> 4, seg = idx & 15;
                cp16(bsOff + (u32)(r * (SAH * 2) + seg * 16), d_emb_h + r * 64 + seg * 4);
            }
            asm volatile("cp.async.commit_group;" ::: "memory");
        }

        // stage A rows (32 x 128 floats) into smem
        {
            const float4* zg = (const float4*)(z + (size_t)rowBase * EDIM);
#pragma unroll
            for (int k = 0; k < 4; k++) {
                int idx = tid + k * 256;              // 0..1023
                int r = idx >> 5, d4 = idx & 31;
                Asf4[r * 33 + d4] = zg[r * 32 + d4];
            }
        }
        __syncthreads();

        // zsq: one thread per row, bit-identical sequential order
        if (tid < TM) {
            const float4* ar = Asf4 + tid * 33;
            float s = 0.f;
#pragma unroll
            for (int q = 0; q < 32; q++) {
                float4 v = ar[q];
                s += v.x * v.x + v.y * v.y + v.z * v.z + v.w * v.w;
            }
            zsmem[tid] = s;
            d_zsq[rowBase + tid] = s;
            sbest[tid] = ~0ULL;
        }
        // convert A to fp16
#pragma unroll
        for (int k = 0; k < 4; k++) {
            int idx = tid + k * 256;
            int r = idx >> 5, d4 = idx & 31;
            float4 v = Asf4[r * 33 + d4];
            A32[r * SAW + d4 * 2]     = h2u(v.x, v.y);
            A32[r * SAW + d4 * 2 + 1] = h2u(v.z, v.w);
        }
        __syncthreads();

        float zrow[2][2];
#pragma unroll
        for (int i = 0; i < 2; i++) {
            zrow[i][0] = zsmem[i * 16 + lr];
            zrow[i][1] = zsmem[i * 16 + lr + 8];
        }

        u64 best1[2][2], best2[2][2];
#pragma unroll
        for (int i = 0; i < 2; i++)
#pragma unroll
            for (int s = 0; s < 2; s++) { best1[i][s] = ~0ULL; best2[i][s] = ~0ULL; }

#pragma unroll 1
        for (int tile = 0; tile < N_TILES; tile++) {
            const int st = tile & 1;
            const int colBase = tile * TN;

            float eq[2][2];
#pragma unroll
            for (int j = 0; j < 2; j++) {
                int c0 = colBase + wn + j * 8 + 2 * lc;
                eq[j][0] = d_esq[c0];
                eq[j][1] = d_esq[c0 + 1];
            }

            if (tile + 1 < N_TILES) {
                const u32* src = d_emb_h + (size_t)(colBase + TN) * 64;
                u32 dstb = bsOff + (st ^ 1) * STAGE_BYTES;
#pragma unroll
                for (int i = 0; i < 8; i++) {
                    int idx = tid + i * 256;
                    int r = idx >> 4, seg = idx & 15;
                    cp16(dstb + (u32)(r * (SAH * 2) + seg * 16), src + r * 64 + seg * 4);
                }
                asm volatile("cp.async.commit_group;" ::: "memory");
                asm volatile("cp.async.wait_group 1;" ::: "memory");
            } else {
                asm volatile("cp.async.wait_group 0;" ::: "memory");
            }
            __syncthreads();

            const u32 bSt = bsOff + st * STAGE_BYTES;

            u32 acc[2][2][2];
#pragma unroll
            for (int i = 0; i < 2; i++)
#pragma unroll
                for (int j = 0; j < 2; j++) { acc[i][j][0] = 0u; acc[i][j][1] = 0u; }

#pragma unroll
            for (int kb = 0; kb < 8; kb++) {
                const u32 kOff = (u32)kb * 32;
                u32 af[2][4], bf[4];
#pragma unroll
                for (int i = 0; i < 2; i++) ldsm4(af[i], aBase[i] + kOff);
                ldsm4(bf, bSt + bBase + kOff);
#pragma unroll
                for (int i = 0; i < 2; i++) {
                    mma16h(acc[i][0], af[i], &bf[0]);
                    mma16h(acc[i][1], af[i], &bf[2]);
                }
            }

            // grid-exact approx epilogue, top-2 per thread
#pragma unroll
            for (int i = 0; i < 2; i++) {
#pragma unroll
                for (int j = 0; j < 2; j++) {
                    int cg0 = colBase + wn + j * 8 + 2 * lc;
                    float2 g0 = __half22float2(*(__half2*)&acc[i][j][0]);  // row lr
                    float2 g1 = __half22float2(*(__half2*)&acc[i][j][1]);  // row lr+8
                    {
                        float d0 = (zrow[i][0] + eq[j][0]) - 2.f * g0.x;
                        float d1 = (zrow[i][0] + eq[j][1]) - 2.f * g0.y;
                        top2(best1[i][0], best2[i][0], ((u64)fkey(d0) << 13) | (u32)cg0);
                        top2(best1[i][0], best2[i][0], ((u64)fkey(d1) << 13) | (u32)(cg0 + 1));
                    }
                    {
                        float d0 = (zrow[i][1] + eq[j][0]) - 2.f * g1.x;
                        float d1 = (zrow[i][1] + eq[j][1]) - 2.f * g1.y;
                        top2(best1[i][1], best2[i][1], ((u64)fkey(d0) << 13) | (u32)cg0);
                        top2(best1[i][1], best2[i][1], ((u64)fkey(d1) << 13) | (u32)(cg0 + 1));
                    }
                }
            }
            __syncthreads();
        }

        // write candidates (64 slots/row) + per-row min
        const int slot = wid * 8 + lc * 2;
#pragma unroll
        for (int i = 0; i < 2; i++)
#pragma unroll
            for (int s = 0; s < 2; s++) {
                int rl = i * 16 + lr + s * 8;
                atomicMin(&sbest[rl], best1[i][s]);
                u64* c = &d_cand[(size_t)(rowBase + rl) * 64 + slot];
                c[0] = best1[i][s];
                c[1] = best2[i][s];
            }
        __syncthreads();
        if (tid < TM) d_minkey[rowBase + tid] = sbest[tid];
        __syncthreads();
    }
}

// ---------- fused rescore + gather + sums + counts ----------
__global__ void k_rg(const float* __restrict__ z, const float* __restrict__ emb,
                     float* __restrict__ out) {
    __shared__ float red[8];
    const int w = threadIdx.x >> 5;
    const int lane = threadIdx.x & 31;
    const int r = blockIdx.x * 8 + w;

    u64 mk = d_minkey[r];
    float dmin = unfkey((u32)(mk >> 13));
    u32 thr = fkey(dmin + DELTA);

    u64 mykey = ~0ULL;
#pragma unroll
    for (int it = 0; it < 2; it++) {
        u64 key = d_cand[(size_t)r * 64 + lane + it * 32];
        if ((u32)(key >> 13) <= thr) {
            int idx = (int)(key & 0x1FFFULL);
            const float4* zr = (const float4*)(z + (size_t)r * EDIM);
            const float4* er = (const float4*)(emb + (size_t)idx * EDIM);
            float dot = 0.f;
#pragma unroll
            for (int q = 0; q < 32; q++) {
                float4 a = zr[q], b = er[q];
                dot += a.x * b.x + a.y * b.y + a.z * b.z + a.w * b.w;
            }
            float tt = d_zsq[r] + d_esq[idx];         // fl(zsq+esq)
            float d = tt - 2.f * dot;                 // fl(t - 2*dot): grid-exact
            u64 k2 = ((u64)fkey(d) << 13) | (u32)idx;
            if (k2 < mykey) mykey = k2;
        }
    }
#pragma unroll
    for (int off = 16; off; off >>= 1) {
        u64 o = __shfl_xor_sync(0xffffffffu, mykey, off);
        if (o < mykey) mykey = o;
    }
    const int idx = (int)(mykey & 0x1FFFULL);

    // gather + straight-through output (1 float4 per lane)
    float4 q  = ((const float4*)(emb + (size_t)idx * EDIM))[lane];
    float4 zz = ((const float4*)(z   + (size_t)r   * EDIM))[lane];
    float4 o4;
    float s = 0.f, df;
    df = q.x - zz.x; o4.x = zz.x + df; s += df * df;
    df = q.y - zz.y; o4.y = zz.y + df; s += df * df;
    df = q.z - zz.z; o4.z = zz.z + df; s += df * df;
    df = q.w - zz.w; o4.w = zz.w + df; s += df * df;
    ((float4*)(out + (size_t)r * EDIM))[lane] = o4;
#pragma unroll
    for (int off = 16; off; off >>= 1) s += __shfl_xor_sync(0xffffffffu, s, off);
    if (lane == 0) {
        atomicAdd(&d_counts[idx], 1);
        red[w] = s;
    }
    __syncthreads();
    if (threadIdx.x == 0) {
        float bs = 0.f;
#pragma unroll
        for (int i = 0; i < 8; i++) bs += red[i];
        atomicAdd(&d_sumsq, (double)bs);
    }
}

// ---------- perplexity + commit loss ----------
__global__ void k_final(float* __restrict__ out, int n_rows) {
    __shared__ float red[32];
    float acc = 0.f;
    float invN = 1.f / (float)n_rows;
    for (int k = threadIdx.x; k < K_CODES; k += 1024) {
        float e = (float)d_counts[k] * invN;
        acc += e * logf(e + 1e-8f);
    }
#pragma unroll
    for (int off = 16; off; off >>= 1) acc += __shfl_xor_sync(0xffffffffu, acc, off);
    if ((threadIdx.x & 31) == 0) red[threadIdx.x >> 5] = acc;
    __syncthreads();
    if (threadIdx.x == 0) {
        float t = 0.f;
#pragma unroll
        for (int i = 0; i < 32; i++) t += red[i];
        float m = (float)(d_sumsq / (double)((size_t)n_rows * EDIM));
        out[(size_t)n_rows * EDIM]     = 0.25f * m + m;
        out[(size_t)n_rows * EDIM + 1] = expf(-t);
    }
}

extern "C" void kernel_launch(void* const* d_in, const int* in_sizes, int n_in,
                              void* d_out, int out_size) {
    const float* z   = (const float*)d_in[0];
    const float* emb = (const float*)d_in[1];
    float* out = (float*)d_out;
    int n_rows = in_sizes[0] / EDIM;                  // 32768

    cudaFuncSetAttribute(k_main, cudaFuncAttributeMaxDynamicSharedMemorySize, SMEM_TOTAL);

    k_init<<<K_CODES / 256, 256>>>(emb);
    k_main<<<296, 256, SMEM_TOTAL>>>(z, emb);
    k_rg<<<n_rows / 8, 256>>>(z, emb, out);
    k_final<<<1, 1024>>>(out, n_rows);
}

// round 10
// speedup vs baseline: 1.9335x; 1.0858x over previous
#include <cuda_runtime.h>
#include <cuda_fp16.h>

typedef unsigned long long u64;
typedef unsigned int u32;

#define K_CODES 8192
#define EDIM 128
#define TM 128
#define TN 128
#define NCHUNK 2048               // codes per CTA
#define NT_LOCAL (NCHUNK / TN)    // 16 inner tiles
#define SAH 136                   // padded row stride (halfs)
#define SAW 68                    // row stride in 32-bit words
#define A_BYTES (128 * SAH * 2)   // 34816
#define STAGE_BYTES (128 * SAH * 2)
#define ZS_OFF (3 * A_BYTES)                 // float[128]
#define SB_OFF (ZS_OFF + 512)                // u64[128]
#define SMEM_TOTAL (120 * 1024)              // pin 1 CTA/SM
#define DELTA 3e-3f

__device__ float  d_esq[K_CODES];
__device__ float  d_zsq[32768];
__device__ __align__(16) u32 d_emb_h[K_CODES * 64];   // fp16 image of emb
__device__ int    d_counts[K_CODES];
__device__ u64    d_minkey[32768];
__device__ u64    d_cand[32768 * 128];
__device__ double d_sumsq;

// ---------------- helpers ----------------
__device__ __forceinline__ u32 smem_u32(const void* p) {
    u32 a; asm("{ .reg .u64 t; cvta.to.shared.u64 t, %1; cvt.u32.u64 %0, t; }" : "=r"(a) : "l"(p));
    return a;
}
__device__ __forceinline__ u32 fkey(float s) {
    u32 b = __float_as_uint(s);
    return (b & 0x80000000u) ? ~b : (b | 0x80000000u);
}
__device__ __forceinline__ float unfkey(u32 k) {
    u32 b = (k & 0x80000000u) ? (k & 0x7FFFFFFFu) : ~k;
    return __uint_as_float(b);
}
__device__ __forceinline__ void cp16(u32 dst, const void* src) {
    asm volatile("cp.async.cg.shared.global [%0], [%1], 16;" :: "r"(dst), "l"(src) : "memory");
}
__device__ __forceinline__ void mma16h(u32* c, const u32* a, const u32* b) {
    asm volatile(
        "mma.sync.aligned.m16n8k16.row.col.f16.f16.f16.f16 "
        "{%0,%1}, {%2,%3,%4,%5}, {%6,%7}, {%0,%1};"
        : "+r"(c[0]), "+r"(c[1])
        : "r"(a[0]), "r"(a[1]), "r"(a[2]), "r"(a[3]), "r"(b[0]), "r"(b[1]));
}
__device__ __forceinline__ void ldsm4(u32* r, u32 addr) {
    asm volatile("ldmatrix.sync.aligned.m8n8.x4.shared.b16 {%0,%1,%2,%3}, [%4];"
        : "=r"(r[0]), "=r"(r[1]), "=r"(r[2]), "=r"(r[3]) : "r"(addr));
}
__device__ __forceinline__ u32 h2u(float x, float y) {
    __half2 h = __floats2half2_rn(x, y);
    return *(u32*)&h;
}
__device__ __forceinline__ void top2(u64& b1, u64& b2, u64 k) {
    if (k < b1) { b2 = b1; b1 = k; }
    else if (k < b2) { b2 = k; }
}

// ---------- kernel 0: |e_k|^2, fp16 emb image, init minkeys/counts ----------
__global__ void k_init(const float* __restrict__ emb) {
    int k = blockIdx.x * blockDim.x + threadIdx.x;    // 0..32767
    if (k < K_CODES) {
        const float4* row = (const float4*)(emb + (size_t)k * EDIM);
        float s = 0.f;
#pragma unroll
        for (int i = 0; i < EDIM / 4; i++) {
            float4 v = row[i];
            s += v.x * v.x + v.y * v.y + v.z * v.z + v.w * v.w;
            d_emb_h[k * 64 + i * 2]     = h2u(v.x, v.y);
            d_emb_h[k * 64 + i * 2 + 1] = h2u(v.z, v.w);
        }
        d_esq[k] = s;
        d_counts[k] = 0;
    }
    d_minkey[k] = ~0ULL;
    if (blockIdx.x == 0 && threadIdx.x == 0) d_sumsq = 0.0;
}

// ---------- main: fp16 screening GEMM, N-split x4 for packing ----------
extern "C" __global__ void __launch_bounds__(256, 1)
k_main(const float* __restrict__ z, const float* __restrict__ emb) {
    extern __shared__ char smem[];
    u32*   A32   = (u32*)smem;                        // [128][68] half2 words
    float* zsmem = (float*)(smem + ZS_OFF);           // [128]
    u64*   sbest = (u64*)(smem + SB_OFF);             // [128]

    const int tid  = threadIdx.x;
    const int wid  = tid >> 5;
    const int lane = tid & 31;
    const int lr   = lane >> 2;
    const int lc   = lane & 3;
    const int wm   = (wid & 1) * 64;
    const int wn   = (wid >> 1) * 32;
    const int rowBase = (blockIdx.x >> 2) * TM;
    const int nchunk  = blockIdx.x & 3;
    const int colOrg  = nchunk * NCHUNK;

    const u32 smb   = smem_u32(smem);
    const u32 bsOff = smb + A_BYTES;

    // ldmatrix base addresses (byte offsets); kb adds 32B per k-step
    u32 aBase[4], bBase[2];
#pragma unroll
    for (int i = 0; i < 4; i++)
        aBase[i] = smb + ((u32)((wm + i * 16 + ((lane >> 3) & 1) * 8 + (lane & 7)) * SAW
                   + (lane >> 4) * 4)) * 4;
#pragma unroll
    for (int jj = 0; jj < 2; jj++)
        bBase[jj] = (u32)((wn + jj * 16 + ((lane >> 4) & 1) * 8 + (lane & 7)) * SAW
                   + ((lane >> 3) & 1) * 4) * 4;

    // prefetch first B tile
    {
        const u32* src = d_emb_h + (size_t)colOrg * 64;
#pragma unroll
        for (int i = 0; i < 8; i++) {
            int idx = tid + i * 256;
            int r = idx >> 4, seg = idx & 15;
            cp16(bsOff + (u32)(r * (SAH * 2) + seg * 16), src + r * 64 + seg * 4);
        }
        asm volatile("cp.async.commit_group;" ::: "memory");
    }

    // prologue: zsq (exact, sequential order) + A fp16 conversion
    if (tid < 128) {
        const float4* zr = (const float4*)(z + (size_t)(rowBase + tid) * EDIM);
        float s = 0.f;
#pragma unroll
        for (int q = 0; q < 32; q++) {
            float4 v = zr[q];
            s += v.x * v.x + v.y * v.y + v.z * v.z + v.w * v.w;
            A32[tid * SAW + q * 2]     = h2u(v.x, v.y);
            A32[tid * SAW + q * 2 + 1] = h2u(v.z, v.w);
        }
        d_zsq[rowBase + tid] = s;
        zsmem[tid] = s;
        sbest[tid] = ~0ULL;
    }
    __syncthreads();

    float zrow[4][2];
#pragma unroll
    for (int i = 0; i < 4; i++) {
        zrow[i][0] = zsmem[wm + i * 16 + lr];
        zrow[i][1] = zsmem[wm + i * 16 + lr + 8];
    }

    u64 best1[4][2], best2[4][2];
#pragma unroll
    for (int i = 0; i < 4; i++)
#pragma unroll
        for (int s = 0; s < 2; s++) { best1[i][s] = ~0ULL; best2[i][s] = ~0ULL; }

#pragma unroll 1
    for (int tile = 0; tile < NT_LOCAL; tile++) {
        const int st = tile & 1;
        const int colBase = colOrg + tile * TN;

        float eq[4][2];
#pragma unroll
        for (int j = 0; j < 4; j++) {
            int c0 = colBase + wn + j * 8 + 2 * lc;
            eq[j][0] = d_esq[c0];
            eq[j][1] = d_esq[c0 + 1];
        }

        if (tile + 1 < NT_LOCAL) {
            const u32* src = d_emb_h + (size_t)(colBase + TN) * 64;
            u32 dstb = bsOff + (st ^ 1) * STAGE_BYTES;
#pragma unroll
            for (int i = 0; i < 8; i++) {
                int idx = tid + i * 256;
                int r = idx >> 4, seg = idx & 15;
                cp16(dstb + (u32)(r * (SAH * 2) + seg * 16), src + r * 64 + seg * 4);
            }
            asm volatile("cp.async.commit_group;" ::: "memory");
            asm volatile("cp.async.wait_group 1;" ::: "memory");
        } else {
            asm volatile("cp.async.wait_group 0;" ::: "memory");
        }
        __syncthreads();

        const u32 bSt = bsOff + st * STAGE_BYTES;

        u32 acc[4][4][2];
#pragma unroll
        for (int i = 0; i < 4; i++)
#pragma unroll
            for (int j = 0; j < 4; j++) { acc[i][j][0] = 0u; acc[i][j][1] = 0u; }

#pragma unroll
        for (int kb = 0; kb < 8; kb++) {
            const u32 kOff = (u32)kb * 32;
            u32 af[4][4], bf[2][4];
#pragma unroll
            for (int i = 0; i < 4; i++) ldsm4(af[i], aBase[i] + kOff);
#pragma unroll
            for (int jj = 0; jj < 2; jj++) ldsm4(bf[jj], bSt + bBase[jj] + kOff);
#pragma unroll
            for (int i = 0; i < 4; i++) {
                mma16h(acc[i][0], af[i], &bf[0][0]);
                mma16h(acc[i][1], af[i], &bf[0][2]);
                mma16h(acc[i][2], af[i], &bf[1][0]);
                mma16h(acc[i][3], af[i], &bf[1][2]);
            }
        }

        // grid-exact approx epilogue, top-2 per thread
#pragma unroll
        for (int i = 0; i < 4; i++) {
#pragma unroll
            for (int j = 0; j < 4; j++) {
                int cg0 = colBase + wn + j * 8 + 2 * lc;
                float2 g0 = __half22float2(*(__half2*)&acc[i][j][0]);  // row lr
                float2 g1 = __half22float2(*(__half2*)&acc[i][j][1]);  // row lr+8
                {
                    float d0 = (zrow[i][0] + eq[j][0]) - 2.f * g0.x;
                    float d1 = (zrow[i][0] + eq[j][1]) - 2.f * g0.y;
                    top2(best1[i][0], best2[i][0], ((u64)fkey(d0) << 13) | (u32)cg0);
                    top2(best1[i][0], best2[i][0], ((u64)fkey(d1) << 13) | (u32)(cg0 + 1));
                }
                {
                    float d0 = (zrow[i][1] + eq[j][0]) - 2.f * g1.x;
                    float d1 = (zrow[i][1] + eq[j][1]) - 2.f * g1.y;
                    top2(best1[i][1], best2[i][1], ((u64)fkey(d0) << 13) | (u32)cg0);
                    top2(best1[i][1], best2[i][1], ((u64)fkey(d1) << 13) | (u32)(cg0 + 1));
                }
            }
        }
        __syncthreads();
    }

    // candidates: this CTA owns 32 slots/row at offset nchunk*32
    const int slot = (wid >> 1) * 4 + lc;             // 0..15 per row
#pragma unroll
    for (int i = 0; i < 4; i++)
#pragma unroll
        for (int s = 0; s < 2; s++) {
            int rl = wm + i * 16 + lr + s * 8;
            atomicMin(&sbest[rl], best1[i][s]);
            u64* c = &d_cand[(size_t)(rowBase + rl) * 128 + nchunk * 32 + slot * 2];
            c[0] = best1[i][s];
            c[1] = best2[i][s];
        }
    __syncthreads();
    if (tid < 128) atomicMin(&d_minkey[rowBase + tid], sbest[tid]);
}

// ---------- fused rescore + gather + sums + counts ----------
__global__ void k_rg(const float* __restrict__ z, const float* __restrict__ emb,
                     float* __restrict__ out) {
    __shared__ float red[8];
    const int w = threadIdx.x >> 5;
    const int lane = threadIdx.x & 31;
    const int r = blockIdx.x * 8 + w;

    u64 mk = d_minkey[r];
    float dmin = unfkey((u32)(mk >> 13));
    u32 thr = fkey(dmin + DELTA);

    u64 mykey = ~0ULL;
#pragma unroll
    for (int it = 0; it < 4; it++) {
        u64 key = d_cand[(size_t)r * 128 + lane + it * 32];
        if ((u32)(key >> 13) <= thr) {
            int idx = (int)(key & 0x1FFFULL);
            const float4* zr = (const float4*)(z + (size_t)r * EDIM);
            const float4* er = (const float4*)(emb + (size_t)idx * EDIM);
            float dot = 0.f;
#pragma unroll
            for (int q = 0; q < 32; q++) {
                float4 a = zr[q], b = er[q];
                dot += a.x * b.x + a.y * b.y + a.z * b.z + a.w * b.w;
            }
            float tt = d_zsq[r] + d_esq[idx];         // fl(zsq+esq)
            float d = tt - 2.f * dot;                 // fl(t - 2*dot): grid-exact
            u64 k2 = ((u64)fkey(d) << 13) | (u32)idx;
            if (k2 < mykey) mykey = k2;
        }
    }
#pragma unroll
    for (int off = 16; off; off >>= 1) {
        u64 o = __shfl_xor_sync(0xffffffffu, mykey, off);
        if (o < mykey) mykey = o;
    }
    const int idx = (int)(mykey & 0x1FFFULL);

    // gather + straight-through output (1 float4 per lane)
    float4 q  = ((const float4*)(emb + (size_t)idx * EDIM))[lane];
    float4 zz = ((const float4*)(z   + (size_t)r   * EDIM))[lane];
    float4 o4;
    float s = 0.f, df;
    df = q.x - zz.x; o4.x = zz.x + df; s += df * df;
    df = q.y - zz.y; o4.y = zz.y + df; s += df * df;
    df = q.z - zz.z; o4.z = zz.z + df; s += df * df;
    df = q.w - zz.w; o4.w = zz.w + df; s += df * df;
    ((float4*)(out + (size_t)r * EDIM))[lane] = o4;
#pragma unroll
    for (int off = 16; off; off >>= 1) s += __shfl_xor_sync(0xffffffffu, s, off);
    if (lane == 0) {
        atomicAdd(&d_counts[idx], 1);
        red[w] = s;
    }
    __syncthreads();
    if (threadIdx.x == 0) {
        float bs = 0.f;
#pragma unroll
        for (int i = 0; i < 8; i++) bs += red[i];
        atomicAdd(&d_sumsq, (double)bs);
    }
}

// ---------- perplexity + commit loss ----------
__global__ void k_final(float* __restrict__ out, int n_rows) {
    __shared__ float red[32];
    float acc = 0.f;
    float invN = 1.f / (float)n_rows;
    for (int k = threadIdx.x; k < K_CODES; k += 1024) {
        float e = (float)d_counts[k] * invN;
        acc += e * logf(e + 1e-8f);
    }
#pragma unroll
    for (int off = 16; off; off >>= 1) acc += __shfl_xor_sync(0xffffffffu, acc, off);
    if ((threadIdx.x & 31) == 0) red[threadIdx.x >> 5] = acc;
    __syncthreads();
    if (threadIdx.x == 0) {
        float t = 0.f;
#pragma unroll
        for (int i = 0; i < 32; i++) t += red[i];
        float m = (float)(d_sumsq / (double)((size_t)n_rows * EDIM));
        out[(size_t)n_rows * EDIM]     = 0.25f * m + m;
        out[(size_t)n_rows * EDIM + 1] = expf(-t);
    }
}

extern "C" void kernel_launch(void* const* d_in, const int* in_sizes, int n_in,
                              void* d_out, int out_size) {
    const float* z   = (const float*)d_in[0];
    const float* emb = (const float*)d_in[1];
    float* out = (float*)d_out;
    int n_rows = in_sizes[0] / EDIM;                  // 32768

    cudaFuncSetAttribute(k_main, cudaFuncAttributeMaxDynamicSharedMemorySize, SMEM_TOTAL);

    k_init<<<32768 / 256, 256>>>(emb);
    k_main<<<(n_rows / TM) * 4, 256, SMEM_TOTAL>>>(z, emb);
    k_rg<<<n_rows / 8, 256>>>(z, emb, out);
    k_final<<<1, 1024>>>(out, n_rows);
}

// round 11
// speedup vs baseline: 1.9345x; 1.0005x over previous
#include <cuda_runtime.h>
#include <cuda_fp16.h>

typedef unsigned long long u64;
typedef unsigned int u32;

#define K_CODES 8192
#define EDIM 128
#define TM 128
#define TN 128
#define NCHUNK 2048               // codes per CTA
#define NT_LOCAL (NCHUNK / TN)    // 16 inner tiles
#define SAH 136                   // padded row stride (halfs)
#define SAW 68                    // row stride in 32-bit words
#define A_BYTES (128 * SAH * 2)   // 34816
#define STAGE_BYTES (128 * SAH * 2)
#define ZS_OFF (3 * A_BYTES)                 // float[128]
#define SB_OFF (ZS_OFF + 512)                // u64[128]
#define SMEM_TOTAL (120 * 1024)              // pin 1 CTA/SM
#define DELTA 3e-3f
#define N_ROWS 32768

__device__ float  d_esq[K_CODES];
__device__ float  d_zsq[N_ROWS];
__device__ __align__(16) u32 d_emb_h[K_CODES * 64];   // fp16 image of emb
__device__ __align__(16) u32 d_z_h[N_ROWS * 64];      // fp16 image of z
__device__ int    d_counts[K_CODES];
__device__ u64    d_minkey[N_ROWS];
__device__ u64    d_cand[N_ROWS * 128];
__device__ double d_sumsq;
__device__ u32    d_rgdone;

// ---------------- helpers ----------------
__device__ __forceinline__ u32 smem_u32(const void* p) {
    u32 a; asm("{ .reg .u64 t; cvta.to.shared.u64 t, %1; cvt.u32.u64 %0, t; }" : "=r"(a) : "l"(p));
    return a;
}
__device__ __forceinline__ u32 fkey(float s) {
    u32 b = __float_as_uint(s);
    return (b & 0x80000000u) ? ~b : (b | 0x80000000u);
}
__device__ __forceinline__ float unfkey(u32 k) {
    u32 b = (k & 0x80000000u) ? (k & 0x7FFFFFFFu) : ~k;
    return __uint_as_float(b);
}
__device__ __forceinline__ void cp16(u32 dst, const void* src) {
    asm volatile("cp.async.cg.shared.global [%0], [%1], 16;" :: "r"(dst), "l"(src) : "memory");
}
__device__ __forceinline__ void mma16h(u32* c, const u32* a, const u32* b) {
    asm volatile(
        "mma.sync.aligned.m16n8k16.row.col.f16.f16.f16.f16 "
        "{%0,%1}, {%2,%3,%4,%5}, {%6,%7}, {%0,%1};"
        : "+r"(c[0]), "+r"(c[1])
        : "r"(a[0]), "r"(a[1]), "r"(a[2]), "r"(a[3]), "r"(b[0]), "r"(b[1]));
}
__device__ __forceinline__ void ldsm4(u32* r, u32 addr) {
    asm volatile("ldmatrix.sync.aligned.m8n8.x4.shared.b16 {%0,%1,%2,%3}, [%4];"
        : "=r"(r[0]), "=r"(r[1]), "=r"(r[2]), "=r"(r[3]) : "r"(addr));
}
__device__ __forceinline__ u32 h2u(float x, float y) {
    __half2 h = __floats2half2_rn(x, y);
    return *(u32*)&h;
}
__device__ __forceinline__ void top2(u64& b1, u64& b2, u64 k) {
    if (k < b1) { b2 = b1; b1 = k; }
    else if (k < b2) { b2 = k; }
}

// ---------- kernel 0: z fp16 image + zsq; emb fp16 image + esq; inits ----------
__global__ void k_init(const float* __restrict__ z, const float* __restrict__ emb) {
    int k = blockIdx.x * blockDim.x + threadIdx.x;    // 0..32767
    // z row k: zsq (sequential order — reference-grid-exact) + fp16 image
    {
        const float4* row = (const float4*)(z + (size_t)k * EDIM);
        float s = 0.f;
#pragma unroll
        for (int i = 0; i < EDIM / 4; i++) {
            float4 v = row[i];
            s += v.x * v.x + v.y * v.y + v.z * v.z + v.w * v.w;
            d_z_h[k * 64 + i * 2]     = h2u(v.x, v.y);
            d_z_h[k * 64 + i * 2 + 1] = h2u(v.z, v.w);
        }
        d_zsq[k] = s;
    }
    if (k < K_CODES) {
        const float4* row = (const float4*)(emb + (size_t)k * EDIM);
        float s = 0.f;
#pragma unroll
        for (int i = 0; i < EDIM / 4; i++) {
            float4 v = row[i];
            s += v.x * v.x + v.y * v.y + v.z * v.z + v.w * v.w;
            d_emb_h[k * 64 + i * 2]     = h2u(v.x, v.y);
            d_emb_h[k * 64 + i * 2 + 1] = h2u(v.z, v.w);
        }
        d_esq[k] = s;
        d_counts[k] = 0;
    }
    d_minkey[k] = ~0ULL;
    if (blockIdx.x == 0 && threadIdx.x == 0) { d_sumsq = 0.0; d_rgdone = 0; }
}

// ---------- main: fp16 screening GEMM, N-split x4 ----------
extern "C" __global__ void __launch_bounds__(256, 1)
k_main(const float* __restrict__ z, const float* __restrict__ emb) {
    extern __shared__ char smem[];
    float* zsmem = (float*)(smem + ZS_OFF);           // [128]
    u64*   sbest = (u64*)(smem + SB_OFF);             // [128]

    const int tid  = threadIdx.x;
    const int wid  = tid >> 5;
    const int lane = tid & 31;
    const int lr   = lane >> 2;
    const int lc   = lane & 3;
    const int wm   = (wid & 1) * 64;
    const int wn   = (wid >> 1) * 32;
    const int rowBase = (blockIdx.x >> 2) * TM;
    const int nchunk  = blockIdx.x & 3;
    const int colOrg  = nchunk * NCHUNK;

    const u32 smb   = smem_u32(smem);
    const u32 bsOff = smb + A_BYTES;

    // ldmatrix base addresses (byte offsets); kb adds 32B per k-step
    u32 aBase[4], bBase[2];
#pragma unroll
    for (int i = 0; i < 4; i++)
        aBase[i] = smb + ((u32)((wm + i * 16 + ((lane >> 3) & 1) * 8 + (lane & 7)) * SAW
                   + (lane >> 4) * 4)) * 4;
#pragma unroll
    for (int jj = 0; jj < 2; jj++)
        bBase[jj] = (u32)((wn + jj * 16 + ((lane >> 4) & 1) * 8 + (lane & 7)) * SAW
                   + ((lane >> 3) & 1) * 4) * 4;

    // prefetch A tile (fp16 image of z rows) + first B tile, one group
    {
        const u32* srcA = d_z_h + (size_t)rowBase * 64;
#pragma unroll
        for (int i = 0; i < 8; i++) {
            int idx = tid + i * 256;                  // 0..2047
            int r = idx >> 4, seg = idx & 15;
            cp16(smb + (u32)(r * (SAH * 2) + seg * 16), srcA + r * 64 + seg * 4);
        }
        const u32* srcB = d_emb_h + (size_t)colOrg * 64;
#pragma unroll
        for (int i = 0; i < 8; i++) {
            int idx = tid + i * 256;
            int r = idx >> 4, seg = idx & 15;
            cp16(bsOff + (u32)(r * (SAH * 2) + seg * 16), srcB + r * 64 + seg * 4);
        }
        asm volatile("cp.async.commit_group;" ::: "memory");
    }

    // zsq + per-row best init
    if (tid < 128) {
        zsmem[tid] = d_zsq[rowBase + tid];
        sbest[tid] = ~0ULL;
    }
    __syncthreads();

    float zrow[4][2];
#pragma unroll
    for (int i = 0; i < 4; i++) {
        zrow[i][0] = zsmem[wm + i * 16 + lr];
        zrow[i][1] = zsmem[wm + i * 16 + lr + 8];
    }

    u64 best1[4][2], best2[4][2];
#pragma unroll
    for (int i = 0; i < 4; i++)
#pragma unroll
        for (int s = 0; s < 2; s++) { best1[i][s] = ~0ULL; best2[i][s] = ~0ULL; }

#pragma unroll 1
    for (int tile = 0; tile < NT_LOCAL; tile++) {
        const int st = tile & 1;
        const int colBase = colOrg + tile * TN;

        float eq[4][2];
#pragma unroll
        for (int j = 0; j < 4; j++) {
            int c0 = colBase + wn + j * 8 + 2 * lc;
            eq[j][0] = d_esq[c0];
            eq[j][1] = d_esq[c0 + 1];
        }

        if (tile + 1 < NT_LOCAL) {
            const u32* src = d_emb_h + (size_t)(colBase + TN) * 64;
            u32 dstb = bsOff + (st ^ 1) * STAGE_BYTES;
#pragma unroll
            for (int i = 0; i < 8; i++) {
                int idx = tid + i * 256;
                int r = idx >> 4, seg = idx & 15;
                cp16(dstb + (u32)(r * (SAH * 2) + seg * 16), src + r * 64 + seg * 4);
            }
            asm volatile("cp.async.commit_group;" ::: "memory");
            asm volatile("cp.async.wait_group 1;" ::: "memory");
        } else {
            asm volatile("cp.async.wait_group 0;" ::: "memory");
        }
        __syncthreads();

        const u32 bSt = bsOff + st * STAGE_BYTES;

        u32 acc[4][4][2];
#pragma unroll
        for (int i = 0; i < 4; i++)
#pragma unroll
            for (int j = 0; j < 4; j++) { acc[i][j][0] = 0u; acc[i][j][1] = 0u; }

#pragma unroll
        for (int kb = 0; kb < 8; kb++) {
            const u32 kOff = (u32)kb * 32;
            u32 af[4][4], bf[2][4];
#pragma unroll
            for (int i = 0; i < 4; i++) ldsm4(af[i], aBase[i] + kOff);
#pragma unroll
            for (int jj = 0; jj < 2; jj++) ldsm4(bf[jj], bSt + bBase[jj] + kOff);
#pragma unroll
            for (int i = 0; i < 4; i++) {
                mma16h(acc[i][0], af[i], &bf[0][0]);
                mma16h(acc[i][1], af[i], &bf[0][2]);
                mma16h(acc[i][2], af[i], &bf[1][0]);
                mma16h(acc[i][3], af[i], &bf[1][2]);
            }
        }

        // grid-exact approx epilogue, top-2 per thread
#pragma unroll
        for (int i = 0; i < 4; i++) {
#pragma unroll
            for (int j = 0; j < 4; j++) {
                int cg0 = colBase + wn + j * 8 + 2 * lc;
                float2 g0 = __half22float2(*(__half2*)&acc[i][j][0]);  // row lr
                float2 g1 = __half22float2(*(__half2*)&acc[i][j][1]);  // row lr+8
                {
                    float d0 = (zrow[i][0] + eq[j][0]) - 2.f * g0.x;
                    float d1 = (zrow[i][0] + eq[j][1]) - 2.f * g0.y;
                    top2(best1[i][0], best2[i][0], ((u64)fkey(d0) << 13) | (u32)cg0);
                    top2(best1[i][0], best2[i][0], ((u64)fkey(d1) << 13) | (u32)(cg0 + 1));
                }
                {
                    float d0 = (zrow[i][1] + eq[j][0]) - 2.f * g1.x;
                    float d1 = (zrow[i][1] + eq[j][1]) - 2.f * g1.y;
                    top2(best1[i][1], best2[i][1], ((u64)fkey(d0) << 13) | (u32)cg0);
                    top2(best1[i][1], best2[i][1], ((u64)fkey(d1) << 13) | (u32)(cg0 + 1));
                }
            }
        }
        __syncthreads();
    }

    // candidates: this CTA owns 32 slots/row at offset nchunk*32
    const int slot = (wid >> 1) * 4 + lc;             // 0..15 per row
#pragma unroll
    for (int i = 0; i < 4; i++)
#pragma unroll
        for (int s = 0; s < 2; s++) {
            int rl = wm + i * 16 + lr + s * 8;
            atomicMin(&sbest[rl], best1[i][s]);
            u64* c = &d_cand[(size_t)(rowBase + rl) * 128 + nchunk * 32 + slot * 2];
            c[0] = best1[i][s];
            c[1] = best2[i][s];
        }
    __syncthreads();
    if (tid < 128) atomicMin(&d_minkey[rowBase + tid], sbest[tid]);
}

// ---------- fused rescore + gather + sums + counts + finale ----------
__global__ void k_rg(const float* __restrict__ z, const float* __restrict__ emb,
                     float* __restrict__ out, int n_rows) {
    __shared__ float red[8];
    __shared__ u32 s_last;
    const int w = threadIdx.x >> 5;
    const int lane = threadIdx.x & 31;
    const int r = blockIdx.x * 8 + w;

    u64 mk = d_minkey[r];
    float dmin = unfkey((u32)(mk >> 13));
    u32 thr = fkey(dmin + DELTA);

    u64 mykey = ~0ULL;
#pragma unroll
    for (int it = 0; it < 4; it++) {
        u64 key = d_cand[(size_t)r * 128 + lane + it * 32];
        if ((u32)(key >> 13) <= thr) {
            int idx = (int)(key & 0x1FFFULL);
            const float4* zr = (const float4*)(z + (size_t)r * EDIM);
            const float4* er = (const float4*)(emb + (size_t)idx * EDIM);
            float dot = 0.f;
#pragma unroll
            for (int q = 0; q < 32; q++) {
                float4 a = zr[q], b = er[q];
                dot += a.x * b.x + a.y * b.y + a.z * b.z + a.w * b.w;
            }
            float tt = d_zsq[r] + d_esq[idx];         // fl(zsq+esq)
            float d = tt - 2.f * dot;                 // fl(t - 2*dot): grid-exact
            u64 k2 = ((u64)fkey(d) << 13) | (u32)idx;
            if (k2 < mykey) mykey = k2;
        }
    }
#pragma unroll
    for (int off = 16; off; off >>= 1) {
        u64 o = __shfl_xor_sync(0xffffffffu, mykey, off);
        if (o < mykey) mykey = o;
    }
    const int idx = (int)(mykey & 0x1FFFULL);

    // gather + straight-through output (1 float4 per lane)
    float4 q  = ((const float4*)(emb + (size_t)idx * EDIM))[lane];
    float4 zz = ((const float4*)(z   + (size_t)r   * EDIM))[lane];
    float4 o4;
    float s = 0.f, df;
    df = q.x - zz.x; o4.x = zz.x + df; s += df * df;
    df = q.y - zz.y; o4.y = zz.y + df; s += df * df;
    df = q.z - zz.z; o4.z = zz.z + df; s += df * df;
    df = q.w - zz.w; o4.w = zz.w + df; s += df * df;
    ((float4*)(out + (size_t)r * EDIM))[lane] = o4;
#pragma unroll
    for (int off = 16; off; off >>= 1) s += __shfl_xor_sync(0xffffffffu, s, off);
    if (lane == 0) {
        atomicAdd(&d_counts[idx], 1);
        red[w] = s;
    }
    __syncthreads();
    if (threadIdx.x == 0) {
        float bs = 0.f;
#pragma unroll
        for (int i = 0; i < 8; i++) bs += red[i];
        atomicAdd(&d_sumsq, (double)bs);
        __threadfence();
        s_last = (atomicAdd(&d_rgdone, 1u) == gridDim.x - 1u) ? 1u : 0u;
    }
    __syncthreads();

    // last block computes perplexity + commit loss
    if (s_last) {
        __threadfence();
        float acc = 0.f;
        float invN = 1.f / (float)n_rows;
        for (int k = threadIdx.x; k < K_CODES; k += 256) {
            float e = (float)d_counts[k] * invN;
            acc += e * logf(e + 1e-8f);
        }
#pragma unroll
        for (int off = 16; off; off >>= 1) acc += __shfl_xor_sync(0xffffffffu, acc, off);
        if (lane == 0) red[w] = acc;
        __syncthreads();
        if (threadIdx.x == 0) {
            float t = 0.f;
#pragma unroll
            for (int i = 0; i < 8; i++) t += red[i];
            double ss = atomicAdd(&d_sumsq, 0.0);
            float m = (float)(ss / (double)((size_t)n_rows * EDIM));
            out[(size_t)n_rows * EDIM]     = 0.25f * m + m;
            out[(size_t)n_rows * EDIM + 1] = expf(-t);
        }
    }
}

extern "C" void kernel_launch(void* const* d_in, const int* in_sizes, int n_in,
                              void* d_out, int out_size) {
    const float* z   = (const float*)d_in[0];
    const float* emb = (const float*)d_in[1];
    float* out = (float*)d_out;
    int n_rows = in_sizes[0] / EDIM;                  // 32768

    cudaFuncSetAttribute(k_main, cudaFuncAttributeMaxDynamicSharedMemorySize, SMEM_TOTAL);

    k_init<<<N_ROWS / 256, 256>>>(z, emb);
    k_main<<<(n_rows / TM) * 4, 256, SMEM_TOTAL>>>(z, emb);
    k_rg<<<n_rows / 8, 256>>>(z, emb, out, n_rows);
}

// round 12
// speedup vs baseline: 2.0040x; 1.0360x over previous
#include <cuda_runtime.h>
#include <cuda_fp16.h>

typedef unsigned long long u64;
typedef unsigned int u32;

#define K_CODES 8192
#define EDIM 128
#define TM 128
#define TN 128
#define NCHUNK 2048               // codes per CTA
#define NT_LOCAL (NCHUNK / TN)    // 16 inner tiles
#define SAH 136                   // padded row stride (halfs)
#define SAW 68                    // row stride in 32-bit words
#define A_BYTES (128 * SAH * 2)   // 34816
#define STAGE_BYTES (128 * SAH * 2)
#define ZS_OFF (3 * A_BYTES)                 // float[128]
#define SB_OFF (ZS_OFF + 512)                // u64[128]
#define SMEM_TOTAL (120 * 1024)              // pin 1 CTA/SM
#define DELTA 3e-3f
#define N_ROWS 32768

__device__ float  d_esq[K_CODES];
__device__ float  d_zsq[N_ROWS];
__device__ __align__(16) u32 d_emb_h[K_CODES * 64];   // fp16 image of emb
__device__ __align__(16) u32 d_z_h[N_ROWS * 64];      // fp16 image of z
__device__ int    d_counts[K_CODES];
__device__ u64    d_minkey[N_ROWS];
__device__ u64    d_cand[N_ROWS * 128];
__device__ double d_sumsq;
__device__ u32    d_rgdone;

// ---------------- helpers ----------------
__device__ __forceinline__ u32 smem_u32(const void* p) {
    u32 a; asm("{ .reg .u64 t; cvta.to.shared.u64 t, %1; cvt.u32.u64 %0, t; }" : "=r"(a) : "l"(p));
    return a;
}
__device__ __forceinline__ u32 fkey(float s) {
    u32 b = __float_as_uint(s);
    return (b & 0x80000000u) ? ~b : (b | 0x80000000u);
}
__device__ __forceinline__ float unfkey(u32 k) {
    u32 b = (k & 0x80000000u) ? (k & 0x7FFFFFFFu) : ~k;
    return __uint_as_float(b);
}
__device__ __forceinline__ void cp16(u32 dst, const void* src) {
    asm volatile("cp.async.cg.shared.global [%0], [%1], 16;" :: "r"(dst), "l"(src) : "memory");
}
__device__ __forceinline__ void mma16h(u32* c, const u32* a, const u32* b) {
    asm volatile(
        "mma.sync.aligned.m16n8k16.row.col.f16.f16.f16.f16 "
        "{%0,%1}, {%2,%3,%4,%5}, {%6,%7}, {%0,%1};"
        : "+r"(c[0]), "+r"(c[1])
        : "r"(a[0]), "r"(a[1]), "r"(a[2]), "r"(a[3]), "r"(b[0]), "r"(b[1]));
}
__device__ __forceinline__ void ldsm4(u32* r, u32 addr) {
    asm volatile("ldmatrix.sync.aligned.m8n8.x4.shared.b16 {%0,%1,%2,%3}, [%4];"
        : "=r"(r[0]), "=r"(r[1]), "=r"(r[2]), "=r"(r[3]) : "r"(addr));
}
__device__ __forceinline__ u32 h2u(float x, float y) {
    __half2 h = __floats2half2_rn(x, y);
    return *(u32*)&h;
}
__device__ __forceinline__ void top2(u64& b1, u64& b2, u64 k) {
    if (k < b1) { b2 = b1; b1 = k; }
    else if (k < b2) { b2 = k; }
}

// ---------- kernel 0: fp16 images + zsq/esq (4 threads/row) ----------
__global__ void k_init(const float* __restrict__ z, const float* __restrict__ emb) {
    int idx = blockIdx.x * blockDim.x + threadIdx.x;  // 0..163839
    if (idx < 131072) {
        int row = idx >> 2, part = idx & 3;
        const float4* src = (const float4*)(z + (size_t)row * EDIM) + part * 8;
        u32* dst = d_z_h + row * 64 + part * 16;
        float s = 0.f;
#pragma unroll
        for (int i = 0; i < 8; i++) {
            float4 v = src[i];
            s += v.x * v.x + v.y * v.y + v.z * v.z + v.w * v.w;
            dst[i * 2]     = h2u(v.x, v.y);
            dst[i * 2 + 1] = h2u(v.z, v.w);
        }
        s += __shfl_xor_sync(0xffffffffu, s, 1);
        s += __shfl_xor_sync(0xffffffffu, s, 2);
        if (part == 0) { d_zsq[row] = s; d_minkey[row] = ~0ULL; }
    } else {
        int e = idx - 131072;                         // 0..32767
        int row = e >> 2, part = e & 3;
        const float4* src = (const float4*)(emb + (size_t)row * EDIM) + part * 8;
        u32* dst = d_emb_h + row * 64 + part * 16;
        float s = 0.f;
#pragma unroll
        for (int i = 0; i < 8; i++) {
            float4 v = src[i];
            s += v.x * v.x + v.y * v.y + v.z * v.z + v.w * v.w;
            dst[i * 2]     = h2u(v.x, v.y);
            dst[i * 2 + 1] = h2u(v.z, v.w);
        }
        s += __shfl_xor_sync(0xffffffffu, s, 1);
        s += __shfl_xor_sync(0xffffffffu, s, 2);
        if (part == 0) { d_esq[row] = s; d_counts[row] = 0; }
    }
    if (idx == 0) { d_sumsq = 0.0; d_rgdone = 0; }
}

// epilogue of one (i,j) fragment pair (grid-exact formula, top-2)
#define EPI_PAIR(ACC, I, J) do {                                              \
    int _cg0 = colP + wn + (J) * 8 + 2 * lc;                                  \
    float2 _g0 = __half22float2(*(__half2*)&ACC[I][J][0]);                    \
    float2 _g1 = __half22float2(*(__half2*)&ACC[I][J][1]);                    \
    float _d0 = (zrow[I][0] + eqP[J][0]) - 2.f * _g0.x;                       \
    float _d1 = (zrow[I][0] + eqP[J][1]) - 2.f * _g0.y;                       \
    top2(best1[I][0], best2[I][0], ((u64)fkey(_d0) << 13) | (u32)_cg0);       \
    top2(best1[I][0], best2[I][0], ((u64)fkey(_d1) << 13) | (u32)(_cg0 + 1)); \
    float _e0 = (zrow[I][1] + eqP[J][0]) - 2.f * _g1.x;                       \
    float _e1 = (zrow[I][1] + eqP[J][1]) - 2.f * _g1.y;                       \
    top2(best1[I][1], best2[I][1], ((u64)fkey(_e0) << 13) | (u32)_cg0);       \
    top2(best1[I][1], best2[I][1], ((u64)fkey(_e1) << 13) | (u32)(_cg0 + 1)); \
} while (0)

// one tile: mma into ACC, interleaved epilogue chunks on ACCP (prev tile)
#define TILE_BODY(ACC, ACCP, TILE) do {                                       \
    const int colBase = colOrg + (TILE) * TN;                                 \
    float eqC[4][2];                                                          \
    _Pragma("unroll") for (int j = 0; j < 4; j++) {                           \
        int c0 = colBase + wn + j * 8 + 2 * lc;                               \
        eqC[j][0] = d_esq[c0]; eqC[j][1] = d_esq[c0 + 1];                     \
    }                                                                         \
    if ((TILE) + 1 < NT_LOCAL) {                                              \
        const u32* src = d_emb_h + (size_t)(colBase + TN) * 64;               \
        u32 dstb = bsOff + (((TILE) + 1) & 1) * STAGE_BYTES;                  \
        _Pragma("unroll") for (int i = 0; i < 8; i++) {                       \
            int idx = tid + i * 256; int r = idx >> 4, seg = idx & 15;        \
            cp16(dstb + (u32)(r * (SAH * 2) + seg * 16), src + r * 64 + seg * 4); \
        }                                                                     \
        asm volatile("cp.async.commit_group;" ::: "memory");                  \
        asm volatile("cp.async.wait_group 1;" ::: "memory");                  \
    } else {                                                                  \
        asm volatile("cp.async.wait_group 0;" ::: "memory");                  \
    }                                                                         \
    __syncthreads();                                                          \
    const u32 bSt = bsOff + ((TILE) & 1) * STAGE_BYTES;                       \
    _Pragma("unroll") for (int i = 0; i < 4; i++)                             \
        _Pragma("unroll") for (int j = 0; j < 4; j++) {                       \
            ACC[i][j][0] = 0u; ACC[i][j][1] = 0u;                             \
        }                                                                     \
    _Pragma("unroll") for (int kb = 0; kb < 8; kb++) {                        \
        const u32 kOff = (u32)kb * 32;                                        \
        u32 af[4][4], bf[2][4];                                               \
        _Pragma("unroll") for (int i = 0; i < 4; i++) ldsm4(af[i], aBase[i] + kOff); \
        _Pragma("unroll") for (int jj = 0; jj < 2; jj++) ldsm4(bf[jj], bSt + bBase[jj] + kOff); \
        _Pragma("unroll") for (int i = 0; i < 4; i++) {                       \
            mma16h(ACC[i][0], af[i], &bf[0][0]);                              \
            mma16h(ACC[i][1], af[i], &bf[0][2]);                              \
            mma16h(ACC[i][2], af[i], &bf[1][0]);                              \
            mma16h(ACC[i][3], af[i], &bf[1][2]);                              \
        }                                                                     \
        if (haveP) {                                                          \
            EPI_PAIR(ACCP, (kb >> 1), ((2 * kb) & 3));                        \
            EPI_PAIR(ACCP, (kb >> 1), ((2 * kb + 1) & 3));                    \
        }                                                                     \
    }                                                                         \
    _Pragma("unroll") for (int j = 0; j < 4; j++) {                           \
        eqP[j][0] = eqC[j][0]; eqP[j][1] = eqC[j][1];                         \
    }                                                                         \
    colP = colBase; haveP = true;                                             \
    __syncthreads();                                                          \
} while (0)

// ---------- main: fp16 screening GEMM, N-split x4, pipelined epilogue ----------
extern "C" __global__ void __launch_bounds__(256, 1)
k_main(const float* __restrict__ z, const float* __restrict__ emb) {
    extern __shared__ char smem[];
    float* zsmem = (float*)(smem + ZS_OFF);           // [128]
    u64*   sbest = (u64*)(smem + SB_OFF);             // [128]

    const int tid  = threadIdx.x;
    const int wid  = tid >> 5;
    const int lane = tid & 31;
    const int lr   = lane >> 2;
    const int lc   = lane & 3;
    const int wm   = (wid & 1) * 64;
    const int wn   = (wid >> 1) * 32;
    const int rowBase = (blockIdx.x >> 2) * TM;
    const int nchunk  = blockIdx.x & 3;
    const int colOrg  = nchunk * NCHUNK;

    const u32 smb   = smem_u32(smem);
    const u32 bsOff = smb + A_BYTES;

    u32 aBase[4], bBase[2];
#pragma unroll
    for (int i = 0; i < 4; i++)
        aBase[i] = smb + ((u32)((wm + i * 16 + ((lane >> 3) & 1) * 8 + (lane & 7)) * SAW
                   + (lane >> 4) * 4)) * 4;
#pragma unroll
    for (int jj = 0; jj < 2; jj++)
        bBase[jj] = (u32)((wn + jj * 16 + ((lane >> 4) & 1) * 8 + (lane & 7)) * SAW
                   + ((lane >> 3) & 1) * 4) * 4;

    // prefetch A tile + first B tile in one group
    {
        const u32* srcA = d_z_h + (size_t)rowBase * 64;
#pragma unroll
        for (int i = 0; i < 8; i++) {
            int idx = tid + i * 256;
            int r = idx >> 4, seg = idx & 15;
            cp16(smb + (u32)(r * (SAH * 2) + seg * 16), srcA + r * 64 + seg * 4);
        }
        const u32* srcB = d_emb_h + (size_t)colOrg * 64;
#pragma unroll
        for (int i = 0; i < 8; i++) {
            int idx = tid + i * 256;
            int r = idx >> 4, seg = idx & 15;
            cp16(bsOff + (u32)(r * (SAH * 2) + seg * 16), srcB + r * 64 + seg * 4);
        }
        asm volatile("cp.async.commit_group;" ::: "memory");
    }

    if (tid < 128) {
        zsmem[tid] = d_zsq[rowBase + tid];
        sbest[tid] = ~0ULL;
    }
    __syncthreads();

    float zrow[4][2];
#pragma unroll
    for (int i = 0; i < 4; i++) {
        zrow[i][0] = zsmem[wm + i * 16 + lr];
        zrow[i][1] = zsmem[wm + i * 16 + lr + 8];
    }

    u64 best1[4][2], best2[4][2];
#pragma unroll
    for (int i = 0; i < 4; i++)
#pragma unroll
        for (int s = 0; s < 2; s++) { best1[i][s] = ~0ULL; best2[i][s] = ~0ULL; }

    u32 accA[4][4][2], accB[4][4][2];
    float eqP[4][2];
    int colP = 0;
    bool haveP = false;

#pragma unroll 1
    for (int t2 = 0; t2 < NT_LOCAL / 2; t2++) {
        TILE_BODY(accA, accB, 2 * t2);
        TILE_BODY(accB, accA, 2 * t2 + 1);
    }
    // final epilogue for tile NT_LOCAL-1 (in accB)
#pragma unroll
    for (int p = 0; p < 16; p++) EPI_PAIR(accB, (p >> 2), (p & 3));

    // candidates: this CTA owns 32 slots/row at offset nchunk*32
    const int slot = (wid >> 1) * 4 + lc;             // 0..15 per row
#pragma unroll
    for (int i = 0; i < 4; i++)
#pragma unroll
        for (int s = 0; s < 2; s++) {
            int rl = wm + i * 16 + lr + s * 8;
            atomicMin(&sbest[rl], best1[i][s]);
            u64* c = &d_cand[(size_t)(rowBase + rl) * 128 + nchunk * 32 + slot * 2];
            c[0] = best1[i][s];
            c[1] = best2[i][s];
        }
    __syncthreads();
    if (tid < 128) atomicMin(&d_minkey[rowBase + tid], sbest[tid]);
}

// ---------- fused rescore + gather + sums + counts + finale ----------
__global__ void k_rg(const float* __restrict__ z, const float* __restrict__ emb,
                     float* __restrict__ out, int n_rows) {
    __shared__ float red[8];
    __shared__ u32 s_last;
    const int w = threadIdx.x >> 5;
    const int lane = threadIdx.x & 31;
    const int r = blockIdx.x * 8 + w;

    u64 mk = d_minkey[r];
    float dmin = unfkey((u32)(mk >> 13));
    u32 thr = fkey(dmin + DELTA);

    u64 mykey = ~0ULL;
#pragma unroll
    for (int it = 0; it < 4; it++) {
        u64 key = d_cand[(size_t)r * 128 + lane + it * 32];
        if ((u32)(key >> 13) <= thr) {
            int idx = (int)(key & 0x1FFFULL);
            const float4* zr = (const float4*)(z + (size_t)r * EDIM);
            const float4* er = (const float4*)(emb + (size_t)idx * EDIM);
            float dot = 0.f;
#pragma unroll
            for (int q = 0; q < 32; q++) {
                float4 a = zr[q], b = er[q];
                dot += a.x * b.x + a.y * b.y + a.z * b.z + a.w * b.w;
            }
            float tt = d_zsq[r] + d_esq[idx];         // fl(zsq+esq)
            float d = tt - 2.f * dot;                 // fl(t - 2*dot): grid-exact
            u64 k2 = ((u64)fkey(d) << 13) | (u32)idx;
            if (k2 < mykey) mykey = k2;
        }
    }
#pragma unroll
    for (int off = 16; off; off >>= 1) {
        u64 o = __shfl_xor_sync(0xffffffffu, mykey, off);
        if (o < mykey) mykey = o;
    }
    const int idx = (int)(mykey & 0x1FFFULL);

    float4 q  = ((const float4*)(emb + (size_t)idx * EDIM))[lane];
    float4 zz = ((const float4*)(z   + (size_t)r   * EDIM))[lane];
    float4 o4;
    float s = 0.f, df;
    df = q.x - zz.x; o4.x = zz.x + df; s += df * df;
    df = q.y - zz.y; o4.y = zz.y + df; s += df * df;
    df = q.z - zz.z; o4.z = zz.z + df; s += df * df;
    df = q.w - zz.w; o4.w = zz.w + df; s += df * df;
    ((float4*)(out + (size_t)r * EDIM))[lane] = o4;
#pragma unroll
    for (int off = 16; off; off >>= 1) s += __shfl_xor_sync(0xffffffffu, s, off);
    if (lane == 0) {
        atomicAdd(&d_counts[idx], 1);
        red[w] = s;
    }
    __syncthreads();
    if (threadIdx.x == 0) {
        float bs = 0.f;
#pragma unroll
        for (int i = 0; i < 8; i++) bs += red[i];
        atomicAdd(&d_sumsq, (double)bs);
        __threadfence();
        s_last = (atomicAdd(&d_rgdone, 1u) == gridDim.x - 1u) ? 1u : 0u;
    }
    __syncthreads();

    if (s_last) {
        __threadfence();
        float acc = 0.f;
        float invN = 1.f / (float)n_rows;
        for (int k = threadIdx.x; k < K_CODES; k += 256) {
            float e = (float)d_counts[k] * invN;
            acc += e * logf(e + 1e-8f);
        }
#pragma unroll
        for (int off = 16; off; off >>= 1) acc += __shfl_xor_sync(0xffffffffu, acc, off);
        if (lane == 0) red[w] = acc;
        __syncthreads();
        if (threadIdx.x == 0) {
            float t = 0.f;
#pragma unroll
            for (int i = 0; i < 8; i++) t += red[i];
            double ss = atomicAdd(&d_sumsq, 0.0);
            float m = (float)(ss / (double)((size_t)n_rows * EDIM));
            out[(size_t)n_rows * EDIM]     = 0.25f * m + m;
            out[(size_t)n_rows * EDIM + 1] = expf(-t);
        }
    }
}

extern "C" void kernel_launch(void* const* d_in, const int* in_sizes, int n_in,
                              void* d_out, int out_size) {
    const float* z   = (const float*)d_in[0];
    const float* emb = (const float*)d_in[1];
    float* out = (float*)d_out;
    int n_rows = in_sizes[0] / EDIM;                  // 32768

    cudaFuncSetAttribute(k_main, cudaFuncAttributeMaxDynamicSharedMemorySize, SMEM_TOTAL);

    k_init<<<640, 256>>>(z, emb);
    k_main<<<(n_rows / TM) * 4, 256, SMEM_TOTAL>>>(z, emb);
    k_rg<<<n_rows / 8, 256>>>(z, emb, out, n_rows);
}